// round 16
// baseline (speedup 1.0000x reference)
#include <cuda_runtime.h>
#include <cuda_fp16.h>
#include <math.h>
#include <stdint.h>

#define T_TOK 4096
#define EMB   1024
#define NEXP  8
#define HID   2048
#define CAP   4096

#define BM 128
#define BN 128
#define BKH 64               // K halves per stage
#define SROW 72              // smem row stride in halves (144B: conflict-free)
#define ASTG (128 * SROW * 2)        // 18432 B per operand per stage
#define STGB (2 * ASTG)              // 36864 B per stage (A+B)
#define NSTG 2
#define GSMEM (NSTG * STGB)          // 73728 B (2 CTAs/SM)

// ---------------- device scratch (no allocations allowed) -------------------
__device__ int    g_counts[NEXP];
__device__ int    g_toks [NEXP * CAP];
__device__ int    g_slot[2 * T_TOK];       // per-token: e*CAP+pos (2 slots)
__device__ float  g_tg  [2 * T_TOK];       // per-token: gate values
__device__ __half g_act[(size_t)NEXP * CAP * EMB];
__device__ __half g_h1 [(size_t)NEXP * CAP * HID];
__device__ __half g_h2 [(size_t)NEXP * CAP * HID];
__device__ __half g_y  [(size_t)NEXP * CAP * EMB];  // expert outputs (fp16)
__device__ __half g_w1t[(size_t)NEXP * HID * EMB];
__device__ __half g_wgt[(size_t)NEXP * HID * HID];
__device__ __half g_w2t[(size_t)NEXP * EMB * HID];

// ---------------- helpers ----------------------------------------------------
__device__ __forceinline__ void cp16(uint32_t dst, const void* src) {
    asm volatile("cp.async.cg.shared.global [%0], [%1], 16;\n" :: "r"(dst), "l"(src));
}
__device__ __forceinline__ uint32_t smem_u32(const void* p) {
    return (uint32_t)__cvta_generic_to_shared(p);
}
__device__ __forceinline__ void ldsm4(uint32_t& r0, uint32_t& r1,
                                      uint32_t& r2, uint32_t& r3, uint32_t a) {
    asm volatile("ldmatrix.sync.aligned.m8n8.x4.shared.b16 {%0,%1,%2,%3}, [%4];"
                 : "=r"(r0), "=r"(r1), "=r"(r2), "=r"(r3) : "r"(a));
}

// ---------------- init ------------------------------------------------------
__global__ void init_counts_kernel() {
    if (threadIdx.x < NEXP) g_counts[threadIdx.x] = 0;
}

// ---------------- fused router + gather: one warp per token -----------------
// Loads the token row once into registers, computes logits/top-2, then writes
// the fp16 row to both expert slots from the same registers.
__global__ void router_gather_kernel(const float* __restrict__ x,
                                     const float* __restrict__ Wr,
                                     const float* __restrict__ br)
{
    int tok  = (blockIdx.x * blockDim.x + threadIdx.x) >> 5;
    int lane = threadIdx.x & 31;
    if (tok >= T_TOK) return;

    const float4* xr = (const float4*)(x + (size_t)tok * EMB);
    float4 v[8];
#pragma unroll
    for (int i = 0; i < 8; i++) v[i] = xr[lane + 32 * i];   // coalesced row load

    float acc[NEXP];
#pragma unroll
    for (int e = 0; e < NEXP; e++) acc[e] = 0.f;
#pragma unroll
    for (int i = 0; i < 8; i++) {
        int base = (lane + 32 * i) * 4;
        const float* f = (const float*)&v[i];
#pragma unroll
        for (int c = 0; c < 4; c++) {
            const float* wrow = Wr + (size_t)(base + c) * NEXP;
            float xv = f[c];
#pragma unroll
            for (int e = 0; e < NEXP; e++) acc[e] += xv * wrow[e];
        }
    }
#pragma unroll
    for (int off = 16; off; off >>= 1)
#pragma unroll
        for (int e = 0; e < NEXP; e++)
            acc[e] += __shfl_xor_sync(0xffffffffu, acc[e], off);

    int s1 = 0, s2 = 0;
    if (lane == 0) {
        float l[NEXP], p[NEXP];
        float mx = -1e30f;
#pragma unroll
        for (int e = 0; e < NEXP; e++) { l[e] = acc[e] + br[e]; mx = fmaxf(mx, l[e]); }
        float s = 0.f;
#pragma unroll
        for (int e = 0; e < NEXP; e++) { p[e] = expf(l[e] - mx); s += p[e]; }
        float inv = 1.f / s;

        int i1 = 0;
#pragma unroll
        for (int e = 1; e < NEXP; e++) if (p[e] > p[i1]) i1 = e;
        int i2 = (i1 == 0) ? 1 : 0;
#pragma unroll
        for (int e = 0; e < NEXP; e++) if (e != i1 && p[e] > p[i2]) i2 = e;

        int pos = atomicAdd(&g_counts[i1], 1);
        s1 = i1 * CAP + pos;
        g_toks[s1] = tok;
        g_slot[2 * tok    ] = s1;
        g_tg  [2 * tok    ] = p[i1] * inv;
        pos = atomicAdd(&g_counts[i2], 1);
        s2 = i2 * CAP + pos;
        g_toks[s2] = tok;
        g_slot[2 * tok + 1] = s2;
        g_tg  [2 * tok + 1] = p[i2] * inv;
    }
    s1 = __shfl_sync(0xffffffffu, s1, 0);
    s2 = __shfl_sync(0xffffffffu, s2, 0);

    // convert row to fp16 (two half2 per float4) and write both slots
    uint2 hv[8];
#pragma unroll
    for (int i = 0; i < 8; i++) {
        __half2 h0 = __floats2half2_rn(v[i].x, v[i].y);
        __half2 h1 = __floats2half2_rn(v[i].z, v[i].w);
        hv[i].x = *(uint32_t*)&h0;
        hv[i].y = *(uint32_t*)&h1;
    }
    uint2* d1 = (uint2*)(g_act + (size_t)s1 * EMB);
    uint2* d2 = (uint2*)(g_act + (size_t)s2 * EMB);
#pragma unroll
    for (int i = 0; i < 8; i++) { d1[lane + 32 * i] = hv[i]; d2[lane + 32 * i] = hv[i]; }
}

// ---------------- final combine: out[t] = g1*y[s1] + g2*y[s2] ---------------
__global__ void combine_kernel(float* __restrict__ out)
{
    int t = blockIdx.x;
    int i = threadIdx.x;                 // 256 threads, 4 floats each
    int   s1 = g_slot[2 * t], s2 = g_slot[2 * t + 1];
    float g1 = g_tg [2 * t], g2 = g_tg [2 * t + 1];
    const __half2* y1 = (const __half2*)(g_y + (size_t)s1 * EMB);
    const __half2* y2 = (const __half2*)(g_y + (size_t)s2 * EMB);
    float2 a0 = __half22float2(y1[2 * i    ]);
    float2 a1 = __half22float2(y1[2 * i + 1]);
    float2 b0 = __half22float2(y2[2 * i    ]);
    float2 b1 = __half22float2(y2[2 * i + 1]);
    float4 o;
    o.x = g1 * a0.x + g2 * b0.x;
    o.y = g1 * a0.y + g2 * b0.y;
    o.z = g1 * a1.x + g2 * b1.x;
    o.w = g1 * a1.y + g2 * b1.y;
    ((float4*)out)[(size_t)t * (EMB / 4) + i] = o;
}

// ---------------- weight transpose-pack: [E][K][N] f32 -> [E][N][K] fp16 ----
template<int K, int N>
__global__ void pack_t_kernel(const float* __restrict__ W, __half* __restrict__ Wt)
{
    __shared__ float s[64][33];
    int e  = blockIdx.z;
    int k0 = blockIdx.x * 64;
    int n0 = blockIdx.y * 32;
    int tid = threadIdx.x;
    const float* src = W + (size_t)e * K * N;
#pragma unroll
    for (int i = 0; i < 8; i++) {
        int idx = tid + i * 256;
        int k = idx >> 5, n = idx & 31;
        s[k][n] = src[(size_t)(k0 + k) * N + n0 + n];
    }
    __syncthreads();
    __half2* dst = (__half2*)(Wt + (size_t)e * N * K);
#pragma unroll
    for (int i = 0; i < 4; i++) {
        int idx = tid + i * 256;
        int n = idx >> 5, j = idx & 31;
        dst[(size_t)(n0 + n) * (K / 2) + k0 / 2 + j] =
            __floats2half2_rn(s[2 * j][n], s[2 * j + 1][n]);
    }
}

// ---------------- grouped FP16 mma.sync GEMM, 128x128, 2-stage --------------
// MODE 0: h1 = A@B^T + b1  MODE 1: h2 = relu(A@B^T+bg)  MODE 2: y = A@B^T + b2
template<int NOUT, int K, int MODE>
__global__ __launch_bounds__(256, 2)
void mma_gemm(const __half* __restrict__ A, const __half* __restrict__ B,
              const float* __restrict__ bias)
{
    const int e   = blockIdx.z;
    const int cnt = g_counts[e];
    const int m0  = blockIdx.y * BM;
    if (m0 >= cnt) return;
    const int n0  = blockIdx.x * BN;

    extern __shared__ __align__(16) char smem_raw[];
    const uint32_t sbase = smem_u32(smem_raw);

    const int tid  = threadIdx.x;
    const int lane = tid & 31;
    const int w    = tid >> 5;
    const int wm   = (w & 1) * 64;
    const int wn   = (w >> 1) * 32;
    const int gr   = lane >> 2;
    const int lc   = lane & 3;

    const __half* Abase = A + (size_t)(e * CAP + m0) * K;
    const __half* Bbase = B + ((size_t)e * NOUT + n0) * K;

    auto load_stage = [&](int j) {
        uint32_t sa = sbase + (j & 1) * STGB;
        uint32_t sb = sa + ASTG;
        const __half* ga = Abase + j * BKH;
        const __half* gb = Bbase + j * BKH;
#pragma unroll
        for (int i = 0; i < 4; i++) {
            int g   = tid + i * 256;
            int row = g >> 3, c = g & 7;
            uint32_t off = (uint32_t)(row * SROW + c * 8) * 2;
            cp16(sa + off, ga + (size_t)row * K + c * 8);
            cp16(sb + off, gb + (size_t)row * K + c * 8);
        }
    };

    const int arow_l = ((lane >> 3) & 1) * 8 + (lane & 7);
    const int akoff  = (lane >> 4) * 8;
    const int brow_l = ((lane >> 4) & 1) * 8 + (lane & 7);
    const int bkoff  = ((lane >> 3) & 1) * 8;

    float acc[4][4][4];
#pragma unroll
    for (int i = 0; i < 4; i++)
#pragma unroll
        for (int j = 0; j < 4; j++)
#pragma unroll
            for (int q = 0; q < 4; q++) acc[i][j][q] = 0.f;

    load_stage(0);
    asm volatile("cp.async.commit_group;\n" ::: "memory");

    const int ITERS = K / BKH;
    for (int it = 0; it < ITERS; it++) {
        if (it + 1 < ITERS) load_stage(it + 1);
        asm volatile("cp.async.commit_group;\n" ::: "memory");
        asm volatile("cp.async.wait_group 1;\n" ::: "memory");
        __syncthreads();

        const uint32_t sa = sbase + (it & 1) * STGB;
        const uint32_t sb = sa + ASTG;
#pragma unroll
        for (int kc = 0; kc < BKH; kc += 16) {
            uint32_t af[4][4], bf[4][2];
#pragma unroll
            for (int i = 0; i < 4; i++) {
                uint32_t a = sa + (uint32_t)((wm + i * 16 + arow_l) * SROW + kc + akoff) * 2;
                ldsm4(af[i][0], af[i][1], af[i][2], af[i][3], a);
            }
            {
                uint32_t t0, t1, t2, t3;
                uint32_t a0 = sb + (uint32_t)((wn + brow_l) * SROW + kc + bkoff) * 2;
                ldsm4(t0, t1, t2, t3, a0);
                bf[0][0] = t0; bf[0][1] = t1; bf[1][0] = t2; bf[1][1] = t3;
                uint32_t a1 = sb + (uint32_t)((wn + 16 + brow_l) * SROW + kc + bkoff) * 2;
                ldsm4(t0, t1, t2, t3, a1);
                bf[2][0] = t0; bf[2][1] = t1; bf[3][0] = t2; bf[3][1] = t3;
            }
#pragma unroll
            for (int i = 0; i < 4; i++)
#pragma unroll
                for (int j = 0; j < 4; j++) {
                    asm volatile(
                        "mma.sync.aligned.m16n8k16.row.col.f32.f16.f16.f32 "
                        "{%0,%1,%2,%3}, {%4,%5,%6,%7}, {%8,%9}, {%0,%1,%2,%3};\n"
                        : "+f"(acc[i][j][0]), "+f"(acc[i][j][1]),
                          "+f"(acc[i][j][2]), "+f"(acc[i][j][3])
                        : "r"(af[i][0]), "r"(af[i][1]), "r"(af[i][2]), "r"(af[i][3]),
                          "r"(bf[j][0]), "r"(bf[j][1]));
                }
        }
        __syncthreads();
    }

    // ---------------- epilogue: fp16 store ----------------
    const float* bp = bias + (size_t)e * NOUT;
    __half* Cb = (MODE == 0) ? g_h1 : (MODE == 1) ? g_h2 : g_y;
#pragma unroll
    for (int i = 0; i < 4; i++)
#pragma unroll
        for (int half = 0; half < 2; half++) {
            int r = m0 + wm + i * 16 + gr + half * 8;
            __half* crow = Cb + (size_t)(e * CAP + r) * NOUT;
#pragma unroll
            for (int j = 0; j < 4; j++) {
                int n = n0 + wn + j * 8 + lc * 2;
                float v0 = acc[i][j][half * 2 + 0] + bp[n];
                float v1 = acc[i][j][half * 2 + 1] + bp[n + 1];
                if (MODE == 1) { v0 = fmaxf(v0, 0.f); v1 = fmaxf(v1, 0.f); }
                *(__half2*)(crow + n) = __floats2half2_rn(v0, v1);
            }
        }
}

// ---------------- launch -----------------------------------------------------
extern "C" void kernel_launch(void* const* d_in, const int* in_sizes, int n_in,
                              void* d_out, int out_size)
{
    const float* x  = (const float*)d_in[0];
    const float* Wr = (const float*)d_in[1];
    const float* br = (const float*)d_in[2];
    const float* W1 = (const float*)d_in[3];
    const float* b1 = (const float*)d_in[4];
    const float* Wg = (const float*)d_in[5];
    const float* bg = (const float*)d_in[6];
    const float* W2 = (const float*)d_in[7];
    const float* b2 = (const float*)d_in[8];
    float* out = (float*)d_out;

    __half *p_act, *p_w1, *p_wg, *p_w2, *p_h1, *p_h2;
    cudaGetSymbolAddress((void**)&p_act, g_act);
    cudaGetSymbolAddress((void**)&p_w1,  g_w1t);
    cudaGetSymbolAddress((void**)&p_wg,  g_wgt);
    cudaGetSymbolAddress((void**)&p_w2,  g_w2t);
    cudaGetSymbolAddress((void**)&p_h1,  g_h1);
    cudaGetSymbolAddress((void**)&p_h2,  g_h2);

    cudaFuncSetAttribute(mma_gemm<HID, EMB, 0>, cudaFuncAttributeMaxDynamicSharedMemorySize, GSMEM);
    cudaFuncSetAttribute(mma_gemm<HID, HID, 1>, cudaFuncAttributeMaxDynamicSharedMemorySize, GSMEM);
    cudaFuncSetAttribute(mma_gemm<EMB, HID, 2>, cudaFuncAttributeMaxDynamicSharedMemorySize, GSMEM);

    init_counts_kernel<<<1, 32>>>();
    router_gather_kernel<<<(T_TOK * 32 + 255) / 256, 256>>>(x, Wr, br);

    pack_t_kernel<EMB, HID><<<dim3(EMB / 64, HID / 32, NEXP), 256>>>(W1, p_w1);
    pack_t_kernel<HID, HID><<<dim3(HID / 64, HID / 32, NEXP), 256>>>(Wg, p_wg);
    pack_t_kernel<HID, EMB><<<dim3(HID / 64, EMB / 32, NEXP), 256>>>(W2, p_w2);

    dim3 blk(256);
    mma_gemm<HID, EMB, 0><<<dim3(HID / BN, CAP / BM, NEXP), blk, GSMEM>>>(p_act, p_w1, b1);
    mma_gemm<HID, HID, 1><<<dim3(HID / BN, CAP / BM, NEXP), blk, GSMEM>>>(p_h1,  p_wg, bg);
    mma_gemm<EMB, HID, 2><<<dim3(EMB / BN, CAP / BM, NEXP), blk, GSMEM>>>(p_h2,  p_w2, b2);

    combine_kernel<<<T_TOK, 256>>>(out);
}

// round 17
// speedup vs baseline: 1.1440x; 1.1440x over previous
#include <cuda_runtime.h>
#include <cuda_fp16.h>
#include <math.h>
#include <stdint.h>

#define T_TOK 4096
#define EMB   1024
#define NEXP  8
#define HID   2048
#define CAP   4096

#define BM 128
#define BN 128
#define BKH 64               // K halves per stage
#define SROW 72              // smem row stride in halves (144B: conflict-free)
#define ASTG (128 * SROW * 2)        // 18432 B per operand per stage
#define STGB (2 * ASTG)              // 36864 B per stage (A+B)
#define GSMEM (2 * STGB)             // 73728 B total (2 stages, 2 CTAs/SM)

// ---------------- device scratch (no allocations allowed) -------------------
__device__ int    g_counts[NEXP];
__device__ int    g_toks [NEXP * CAP];
__device__ float  g_gates[NEXP * CAP];
__device__ __half g_act[(size_t)NEXP * CAP * EMB];   // gathered tokens fp16
__device__ __half g_h1 [(size_t)NEXP * CAP * HID];
__device__ __half g_h2 [(size_t)NEXP * CAP * HID];
__device__ __half g_w1t[(size_t)NEXP * HID * EMB];   // [E][N=HID][K=EMB]
__device__ __half g_wgt[(size_t)NEXP * HID * HID];   // [E][N=HID][K=HID]
__device__ __half g_w2t[(size_t)NEXP * EMB * HID];   // [E][N=EMB][K=HID]

// ---------------- helpers ----------------------------------------------------
__device__ __forceinline__ void cp16(uint32_t dst, const void* src) {
    asm volatile("cp.async.cg.shared.global [%0], [%1], 16;\n" :: "r"(dst), "l"(src));
}
__device__ __forceinline__ uint32_t smem_u32(const void* p) {
    return (uint32_t)__cvta_generic_to_shared(p);
}
__device__ __forceinline__ void ldsm4(uint32_t& r0, uint32_t& r1,
                                      uint32_t& r2, uint32_t& r3, uint32_t a) {
    asm volatile("ldmatrix.sync.aligned.m8n8.x4.shared.b16 {%0,%1,%2,%3}, [%4];"
                 : "=r"(r0), "=r"(r1), "=r"(r2), "=r"(r3) : "r"(a));
}

// ---------------- init ------------------------------------------------------
__global__ void init_counts_kernel() {
    if (threadIdx.x < NEXP) g_counts[threadIdx.x] = 0;
}

// ---------------- router: one warp per token --------------------------------
__global__ void router_kernel(const float* __restrict__ x,
                              const float* __restrict__ Wr,
                              const float* __restrict__ br)
{
    int warp = (blockIdx.x * blockDim.x + threadIdx.x) >> 5;
    int lane = threadIdx.x & 31;
    if (warp >= T_TOK) return;

    const float* xr = x + (size_t)warp * EMB;
    float acc[NEXP];
#pragma unroll
    for (int e = 0; e < NEXP; e++) acc[e] = 0.f;
    for (int i = lane; i < EMB; i += 32) {
        float xv = xr[i];
        const float* wrow = Wr + i * NEXP;
#pragma unroll
        for (int e = 0; e < NEXP; e++) acc[e] += xv * wrow[e];
    }
#pragma unroll
    for (int off = 16; off; off >>= 1)
#pragma unroll
        for (int e = 0; e < NEXP; e++)
            acc[e] += __shfl_xor_sync(0xffffffffu, acc[e], off);

    if (lane == 0) {
        float l[NEXP], p[NEXP];
        float mx = -1e30f;
#pragma unroll
        for (int e = 0; e < NEXP; e++) { l[e] = acc[e] + br[e]; mx = fmaxf(mx, l[e]); }
        float s = 0.f;
#pragma unroll
        for (int e = 0; e < NEXP; e++) { p[e] = expf(l[e] - mx); s += p[e]; }
        float inv = 1.f / s;

        int i1 = 0;
#pragma unroll
        for (int e = 1; e < NEXP; e++) if (p[e] > p[i1]) i1 = e;
        int i2 = (i1 == 0) ? 1 : 0;
#pragma unroll
        for (int e = 0; e < NEXP; e++) if (e != i1 && p[e] > p[i2]) i2 = e;

        int pos = atomicAdd(&g_counts[i1], 1);
        g_toks [i1 * CAP + pos] = warp;
        g_gates[i1 * CAP + pos] = p[i1] * inv;
        pos = atomicAdd(&g_counts[i2], 1);
        g_toks [i2 * CAP + pos] = warp;
        g_gates[i2 * CAP + pos] = p[i2] * inv;
    }
}

// ---------------- gather x rows -> fp16 activation buffer --------------------
__global__ void gather_kernel(const float* __restrict__ x)
{
    int b = blockIdx.x;
    int e = b >> 12;
    int i = b & (CAP - 1);
    if (i >= g_counts[e]) return;
    int tok = g_toks[b];
    const float4* src = (const float4*)(x + (size_t)tok * EMB);
    __half2* dst = (__half2*)(g_act + (size_t)b * EMB);
    int t = threadIdx.x;
    float4 v = src[t];
    dst[2 * t    ] = __floats2half2_rn(v.x, v.y);
    dst[2 * t + 1] = __floats2half2_rn(v.z, v.w);
}

// ---------------- weight transpose-pack: [E][K][N] f32 -> [E][N][K] fp16 ----
template<int K, int N>
__global__ void pack_t_kernel(const float* __restrict__ W, __half* __restrict__ Wt)
{
    __shared__ float s[64][33];
    int e  = blockIdx.z;
    int k0 = blockIdx.x * 64;
    int n0 = blockIdx.y * 32;
    int tid = threadIdx.x;
    const float* src = W + (size_t)e * K * N;
#pragma unroll
    for (int i = 0; i < 8; i++) {
        int idx = tid + i * 256;
        int k = idx >> 5, n = idx & 31;
        s[k][n] = src[(size_t)(k0 + k) * N + n0 + n];
    }
    __syncthreads();
    __half2* dst = (__half2*)(Wt + (size_t)e * N * K);
#pragma unroll
    for (int i = 0; i < 4; i++) {
        int idx = tid + i * 256;
        int n = idx >> 5, j = idx & 31;
        dst[(size_t)(n0 + n) * (K / 2) + k0 / 2 + j] =
            __floats2half2_rn(s[2 * j][n], s[2 * j + 1][n]);
    }
}

// ---------------- grouped FP16 mma.sync GEMM with ldmatrix, 2-stage ---------
// MODE 0: h1 = A@B^T + b1   MODE 1: h2 = relu(A@B^T+bg)   MODE 2: atomic scatter
template<int NOUT, int K, int MODE>
__global__ __launch_bounds__(256, 2)
void mma_gemm(const __half* __restrict__ A, const __half* __restrict__ B,
              const float* __restrict__ bias, float* __restrict__ out)
{
    const int e   = blockIdx.z;
    const int cnt = g_counts[e];
    const int m0  = blockIdx.y * BM;
    if (m0 >= cnt) return;
    const int n0  = blockIdx.x * BN;

    extern __shared__ __align__(16) char smem_raw[];
    const uint32_t sbase = smem_u32(smem_raw);

    const int tid  = threadIdx.x;
    const int lane = tid & 31;
    const int w    = tid >> 5;
    const int wm   = (w & 1) * 64;
    const int wn   = (w >> 1) * 32;
    const int gr   = lane >> 2;
    const int lc   = lane & 3;

    const __half* Abase = A + (size_t)(e * CAP + m0) * K;
    const __half* Bbase = B + ((size_t)e * NOUT + n0) * K;

    auto load_stage = [&](int j) {
        uint32_t sa = sbase + (j & 1) * STGB;
        uint32_t sb = sa + ASTG;
        const __half* ga = Abase + j * BKH;
        const __half* gb = Bbase + j * BKH;
#pragma unroll
        for (int i = 0; i < 4; i++) {
            int g   = tid + i * 256;
            int row = g >> 3, c = g & 7;
            uint32_t off = (uint32_t)(row * SROW + c * 8) * 2;
            cp16(sa + off, ga + (size_t)row * K + c * 8);
            cp16(sb + off, gb + (size_t)row * K + c * 8);
        }
    };

    const int arow_l = ((lane >> 3) & 1) * 8 + (lane & 7);
    const int akoff  = (lane >> 4) * 8;
    const int brow_l = ((lane >> 4) & 1) * 8 + (lane & 7);
    const int bkoff  = ((lane >> 3) & 1) * 8;

    float acc[4][4][4];
#pragma unroll
    for (int i = 0; i < 4; i++)
#pragma unroll
        for (int j = 0; j < 4; j++)
#pragma unroll
            for (int q = 0; q < 4; q++) acc[i][j][q] = 0.f;

    load_stage(0);
    asm volatile("cp.async.commit_group;\n" ::: "memory");

    const int ITERS = K / BKH;
    for (int it = 0; it < ITERS; it++) {
        if (it + 1 < ITERS) load_stage(it + 1);
        asm volatile("cp.async.commit_group;\n" ::: "memory");
        asm volatile("cp.async.wait_group 1;\n" ::: "memory");
        __syncthreads();

        const uint32_t sa = sbase + (it & 1) * STGB;
        const uint32_t sb = sa + ASTG;
#pragma unroll
        for (int kc = 0; kc < BKH; kc += 16) {
            uint32_t af[4][4], bf[4][2];
#pragma unroll
            for (int i = 0; i < 4; i++) {
                uint32_t a = sa + (uint32_t)((wm + i * 16 + arow_l) * SROW + kc + akoff) * 2;
                ldsm4(af[i][0], af[i][1], af[i][2], af[i][3], a);
            }
            {
                uint32_t t0, t1, t2, t3;
                uint32_t a0 = sb + (uint32_t)((wn + brow_l) * SROW + kc + bkoff) * 2;
                ldsm4(t0, t1, t2, t3, a0);
                bf[0][0] = t0; bf[0][1] = t1; bf[1][0] = t2; bf[1][1] = t3;
                uint32_t a1 = sb + (uint32_t)((wn + 16 + brow_l) * SROW + kc + bkoff) * 2;
                ldsm4(t0, t1, t2, t3, a1);
                bf[2][0] = t0; bf[2][1] = t1; bf[3][0] = t2; bf[3][1] = t3;
            }
#pragma unroll
            for (int i = 0; i < 4; i++)
#pragma unroll
                for (int j = 0; j < 4; j++) {
                    asm volatile(
                        "mma.sync.aligned.m16n8k16.row.col.f32.f16.f16.f32 "
                        "{%0,%1,%2,%3}, {%4,%5,%6,%7}, {%8,%9}, {%0,%1,%2,%3};\n"
                        : "+f"(acc[i][j][0]), "+f"(acc[i][j][1]),
                          "+f"(acc[i][j][2]), "+f"(acc[i][j][3])
                        : "r"(af[i][0]), "r"(af[i][1]), "r"(af[i][2]), "r"(af[i][3]),
                          "r"(bf[j][0]), "r"(bf[j][1]));
                }
        }
        __syncthreads();
    }

    // ---------------- epilogue ----------------
    const float* bp = bias + (size_t)e * NOUT;
    if (MODE == 2) {
#pragma unroll
        for (int i = 0; i < 4; i++)
#pragma unroll
            for (int half = 0; half < 2; half++) {
                int r = m0 + wm + i * 16 + gr + half * 8;
                if (r < cnt) {
                    int   tok = g_toks [e * CAP + r];
                    float gv  = g_gates[e * CAP + r];
#pragma unroll
                    for (int j = 0; j < 4; j++) {
                        int n = n0 + wn + j * 8 + lc * 2;
                        float v0 = acc[i][j][half * 2 + 0] + bp[n];
                        float v1 = acc[i][j][half * 2 + 1] + bp[n + 1];
                        atomicAdd(out + (size_t)tok * NOUT + n,     gv * v0);
                        atomicAdd(out + (size_t)tok * NOUT + n + 1, gv * v1);
                    }
                }
            }
    } else {
        __half* Cb = (MODE == 0) ? g_h1 : g_h2;
#pragma unroll
        for (int i = 0; i < 4; i++)
#pragma unroll
            for (int half = 0; half < 2; half++) {
                int r = m0 + wm + i * 16 + gr + half * 8;
                __half* crow = Cb + (size_t)(e * CAP + r) * NOUT;
#pragma unroll
                for (int j = 0; j < 4; j++) {
                    int n = n0 + wn + j * 8 + lc * 2;
                    float v0 = acc[i][j][half * 2 + 0] + bp[n];
                    float v1 = acc[i][j][half * 2 + 1] + bp[n + 1];
                    if (MODE == 1) { v0 = fmaxf(v0, 0.f); v1 = fmaxf(v1, 0.f); }
                    *(__half2*)(crow + n) = __floats2half2_rn(v0, v1);
                }
            }
    }
}

// ---------------- launch: packs overlapped on a second stream ----------------
extern "C" void kernel_launch(void* const* d_in, const int* in_sizes, int n_in,
                              void* d_out, int out_size)
{
    const float* x  = (const float*)d_in[0];
    const float* Wr = (const float*)d_in[1];
    const float* br = (const float*)d_in[2];
    const float* W1 = (const float*)d_in[3];
    const float* b1 = (const float*)d_in[4];
    const float* Wg = (const float*)d_in[5];
    const float* bg = (const float*)d_in[6];
    const float* W2 = (const float*)d_in[7];
    const float* b2 = (const float*)d_in[8];
    float* out = (float*)d_out;

    __half *p_act, *p_w1, *p_wg, *p_w2, *p_h1, *p_h2;
    cudaGetSymbolAddress((void**)&p_act, g_act);
    cudaGetSymbolAddress((void**)&p_w1,  g_w1t);
    cudaGetSymbolAddress((void**)&p_wg,  g_wgt);
    cudaGetSymbolAddress((void**)&p_w2,  g_w2t);
    cudaGetSymbolAddress((void**)&p_h1,  g_h1);
    cudaGetSymbolAddress((void**)&p_h2,  g_h2);

    cudaFuncSetAttribute(mma_gemm<HID, EMB, 0>, cudaFuncAttributeMaxDynamicSharedMemorySize, GSMEM);
    cudaFuncSetAttribute(mma_gemm<HID, HID, 1>, cudaFuncAttributeMaxDynamicSharedMemorySize, GSMEM);
    cudaFuncSetAttribute(mma_gemm<EMB, HID, 2>, cudaFuncAttributeMaxDynamicSharedMemorySize, GSMEM);

    static cudaStream_t s1 = nullptr;
    static cudaEvent_t  eFork = nullptr, eW1 = nullptr, eWg = nullptr, eW2 = nullptr;
    if (s1 == nullptr) {
        cudaStreamCreateWithFlags(&s1, cudaStreamNonBlocking);
        cudaEventCreateWithFlags(&eFork, cudaEventDisableTiming);
        cudaEventCreateWithFlags(&eW1,   cudaEventDisableTiming);
        cudaEventCreateWithFlags(&eWg,   cudaEventDisableTiming);
        cudaEventCreateWithFlags(&eW2,   cudaEventDisableTiming);
    }

    // fork second stream off the (captured) main stream
    cudaEventRecord(eFork, 0);
    cudaStreamWaitEvent(s1, eFork, 0);

    // packs on side stream
    pack_t_kernel<EMB, HID><<<dim3(EMB / 64, HID / 32, NEXP), 256, 0, s1>>>(W1, p_w1);
    cudaEventRecord(eW1, s1);
    pack_t_kernel<HID, HID><<<dim3(HID / 64, HID / 32, NEXP), 256, 0, s1>>>(Wg, p_wg);
    cudaEventRecord(eWg, s1);
    pack_t_kernel<HID, EMB><<<dim3(HID / 64, EMB / 32, NEXP), 256, 0, s1>>>(W2, p_w2);
    cudaEventRecord(eW2, s1);

    // main stream: routing + gather in parallel with packs
    cudaMemsetAsync(out, 0, (size_t)T_TOK * EMB * sizeof(float));
    init_counts_kernel<<<1, 32>>>();
    router_kernel<<<(T_TOK * 32 + 255) / 256, 256>>>(x, Wr, br);
    gather_kernel<<<NEXP * CAP, 256>>>(x);

    dim3 blk(256);
    cudaStreamWaitEvent(0, eW1, 0);
    mma_gemm<HID, EMB, 0><<<dim3(HID / BN, CAP / BM, NEXP), blk, GSMEM>>>(p_act, p_w1, b1, nullptr);
    cudaStreamWaitEvent(0, eWg, 0);
    mma_gemm<HID, HID, 1><<<dim3(HID / BN, CAP / BM, NEXP), blk, GSMEM>>>(p_h1,  p_wg, bg, nullptr);
    cudaStreamWaitEvent(0, eW2, 0);
    mma_gemm<EMB, HID, 2><<<dim3(EMB / BN, CAP / BM, NEXP), blk, GSMEM>>>(p_h2,  p_w2, b2, out);
}